// round 16
// baseline (speedup 1.0000x reference)
#include <cuda_runtime.h>
#include <cuda_bf16.h>
#include <cstdint>

#define BATCH 64
#define HID   1024
#define TLEN  512
#define NCTA  128
#define NTHR  512
#define NCH1  16   // layer1 K chunks of 128 (K = 1024 h0 + 1024 h1)
#define NCH0  9    // layer0 K chunks of 128 (K = 128 x + 1024 h0)

// Pre-tiled, pre-swizzled operands (gate-permuted rows, SW128, hi/lo split).
// Weight blocks per (m,kc64): 16384 elems = [hi-half0 4096 | hi-half1 4096 |
// lo-half0 4096 | lo-half1 4096]?? — layout as R10-R15: [hi 8192 | lo 8192],
// with our 64 rows at +half*4096 within each plane.
__device__ __align__(16) __nv_bfloat16 g_w1[32 * 32 * 16384];
__device__ __align__(16) __nv_bfloat16 g_w0[32 * 18 * 16384];
__device__ __align__(16) __nv_bfloat16 g_xt[TLEN * 2 * 8192];
__device__ __align__(16) __nv_bfloat16 g_h0t[2][16][8192];
__device__ __align__(16) __nv_bfloat16 g_h1t[2][16][8192];
__device__ float g_biasp[2][4096];
__device__ float g_h1final[BATCH * HID];
__device__ unsigned g_bar_count, g_bar_gen;

__host__ __device__ __forceinline__ uint32_t sw128(uint32_t o) {
    return o ^ ((o >> 3) & 0x70);
}

// smem: 3 slots x 64KB. Slot = [A0hi 8K|A0lo 8K|A1hi 8K|A1lo 8K|B 32K].
// Epilogue aliases: trans -> slot0, reduction layers -> slot1.
#define SLOT(s)   ((s) * 65536)
#define SRED      65536
#define REDLAYER  16384
#define SMEM_TOTAL 196608

__device__ __forceinline__ uint32_t smem_u32(const void* p) {
    uint32_t a;
    asm("{ .reg .u64 t; cvta.to.shared.u64 t, %1; cvt.u32.u64 %0, t; }" : "=r"(a) : "l"(p));
    return a;
}
#define CP_ASYNC16(dst_u32, src_ptr) \
    asm volatile("cp.async.cg.shared.global [%0], [%1], 16;" \
                 :: "r"(dst_u32), "l"(src_ptr) : "memory")
#define CP_COMMIT() asm volatile("cp.async.commit_group;" ::: "memory")
#define CP_WAIT1()  asm volatile("cp.async.wait_group 1;" ::: "memory")
#define CP_WAIT0()  asm volatile("cp.async.wait_group 0;" ::: "memory")

#define LDSM_X4(r0, r1, r2, r3, addr) \
    asm volatile("ldmatrix.sync.aligned.m8n8.x4.shared.b16 {%0,%1,%2,%3}, [%4];" \
                 : "=r"(r0), "=r"(r1), "=r"(r2), "=r"(r3) : "r"(addr))

__device__ __forceinline__ void grid_barrier() {
    __syncthreads();
    if (threadIdx.x == 0) {
        __threadfence();
        unsigned gen = *(volatile unsigned*)&g_bar_gen;
        if (atomicAdd(&g_bar_count, 1u) == NCTA - 1) {
            g_bar_count = 0;
            __threadfence();
            *(volatile unsigned*)&g_bar_gen = gen + 1;
        } else {
            while (*(volatile unsigned*)&g_bar_gen == gen) {}
            __threadfence();
        }
    }
    __syncthreads();
}

#define MMA_BF16(d, a0, a1, a2, a3, b0, b1)                                 \
    asm volatile("mma.sync.aligned.m16n8k16.row.col.f32.bf16.bf16.f32 "     \
                 "{%0,%1,%2,%3}, {%4,%5,%6,%7}, {%8,%9}, {%0,%1,%2,%3};"    \
                 : "+f"((d)[0]), "+f"((d)[1]), "+f"((d)[2]), "+f"((d)[3])   \
                 : "r"(a0), "r"(a1), "r"(a2), "r"(a3), "r"(b0), "r"(b1))

// Pre-issue the A pieces of chunk 0 into slot 0 (addresses are step-invariant
// per CTA). One cp.async group.
template <bool ISL1>
__device__ __forceinline__ void preissue_a0(uint32_t sbase, int m, int half) {
    const __nv_bfloat16* wtile = ISL1 ? (g_w1 + m * 32 * 16384)
                                      : (g_w0 + m * 18 * 16384);
    const int tid = threadIdx.x;
    const __nv_bfloat16* p0 = wtile + half * 4096;      // k-tile0 hi
    uint32_t da = sbase + SLOT(0);
    CP_ASYNC16(da +     0 + tid * 16, (const char*)p0 + tid * 16);            // A0hi
    CP_ASYNC16(da +  8192 + tid * 16, (const char*)(p0 + 8192) + tid * 16);   // A0lo
    CP_ASYNC16(da + 16384 + tid * 16, (const char*)(p0 + 16384) + tid * 16);  // A1hi
    CP_ASYNC16(da + 24576 + tid * 16, (const char*)(p0 + 24576) + tid * 16);  // A1lo
    CP_COMMIT();
}

// One step, one CTA: 64 gate rows (= 16 hidden dims) x 64 batches, full K.
// 16 warps = 2 m-groups x 4 K-splits x 2 j-splits. K chunks of 128.
template <int NCH, bool ISL1>
__device__ __forceinline__ void
run_step(char* smem, uint32_t sbase, int mt, int tstep, float* creg)
{
    const int tid  = threadIdx.x;
    const int wid  = tid >> 5, lane = tid & 31;
    const int mg   = wid & 1,  ks   = (wid >> 1) & 3, js = wid >> 3;
    const int r    = lane >> 2, cq  = lane & 3;
    const int m    = mt >> 1,  half = mt & 1;

    const __nv_bfloat16* wtile = ISL1 ? (g_w1 + m * 32 * 16384)
                                      : (g_w0 + m * 18 * 16384);
    // B source for a 128-wide chunk: 2 consecutive 8192-elem tiles (32 KB).
    auto bsrc_of = [&](int kc) -> const __nv_bfloat16* {
        if (ISL1) return (kc < 8) ? &g_h0t[tstep & 1][2 * kc][0]
                                  : &g_h1t[(tstep + 1) & 1][2 * (kc - 8)][0];
        else      return (kc == 0) ? (g_xt + tstep * 16384)
                                   : &g_h0t[(tstep + 1) & 1][2 * (kc - 1)][0];
    };

    auto issue_a = [&](int kc) {
        const int s = kc % 3;
        const __nv_bfloat16* p0 = wtile + kc * 32768 + half * 4096;
        uint32_t da = sbase + SLOT(s);
        CP_ASYNC16(da +     0 + tid * 16, (const char*)p0 + tid * 16);
        CP_ASYNC16(da +  8192 + tid * 16, (const char*)(p0 + 8192) + tid * 16);
        CP_ASYNC16(da + 16384 + tid * 16, (const char*)(p0 + 16384) + tid * 16);
        CP_ASYNC16(da + 24576 + tid * 16, (const char*)(p0 + 24576) + tid * 16);
    };
    auto issue_b = [&](int kc) {
        const int s = kc % 3;
        const char* gb = reinterpret_cast<const char*>(bsrc_of(kc));
        uint32_t db = sbase + SLOT(s) + 32768;
#pragma unroll
        for (int rr = 0; rr < 4; rr++)
            CP_ASYNC16(db + (tid + 512 * rr) * 16, gb + (tid + 512 * rr) * 16);
    };

    float acc[2][4][4];
#pragma unroll
    for (int d = 0; d < 2; d++)
#pragma unroll
        for (int j = 0; j < 4; j++)
#pragma unroll
            for (int q = 0; q < 4; q++) acc[d][j][q] = 0.0f;

    // Chunk-invariant per-lane ldmatrix addresses (validated R14/R15).
    const int grp = lane >> 3, rowin = lane & 7;
    const uint32_t aoff =
        (uint32_t)((mg * 32 + ((grp & 1) << 3) + rowin) * 128) +
        ((uint32_t)(ks * 32 + ((grp >> 1) << 4)) ^ (uint32_t)(rowin << 4));
    const uint32_t boff =
        (uint32_t)((((grp >> 1) << 3) + rowin) * 128) +
        ((uint32_t)(ks * 32 + ((grp & 1) << 4)) ^ (uint32_t)(rowin << 4)) +
        (uint32_t)(js * 4096);

    // Entry: A of chunk 0 already pre-issued (1 group). Add B0, then chunk1.
    issue_b(0); CP_COMMIT();
    if (NCH > 1) { issue_a(1); issue_b(1); CP_COMMIT(); }

    for (int kc = 0; kc < NCH; kc++) {
        if (kc + 1 < NCH) CP_WAIT1(); else CP_WAIT0();
        __syncthreads();                       // slot kc%3 full; kc-1 reads done
        if (kc + 2 < NCH) {                    // overwrites slot (kc-1)%3: safe
            issue_a(kc + 2); issue_b(kc + 2); CP_COMMIT();
        }

        const uint32_t sb = sbase + SLOT(kc % 3);
#pragma unroll
        for (int sub = 0; sub < 2; sub++) {
            const uint32_t aA = sb + sub * 16384 + aoff;          // hi; lo +8192
            const uint32_t aB = sb + 32768 + sub * 16384 + boff;  // hi; lo +8192

            uint32_t ah[2][4], al[2][4];
            LDSM_X4(ah[0][0], ah[0][1], ah[0][2], ah[0][3], aA);
            LDSM_X4(ah[1][0], ah[1][1], ah[1][2], ah[1][3], aA + 2048);
            LDSM_X4(al[0][0], al[0][1], al[0][2], al[0][3], aA + 8192);
            LDSM_X4(al[1][0], al[1][1], al[1][2], al[1][3], aA + 8192 + 2048);

            // passes 1+2: (Ahi + Alo) x Bhi
#pragma unroll
            for (int p = 0; p < 2; p++) {
                uint32_t b0, b1, b2, b3;
                LDSM_X4(b0, b1, b2, b3, aB + p * 2048);
                MMA_BF16(acc[0][2*p],   ah[0][0], ah[0][1], ah[0][2], ah[0][3], b0, b1);
                MMA_BF16(acc[1][2*p],   ah[1][0], ah[1][1], ah[1][2], ah[1][3], b0, b1);
                MMA_BF16(acc[0][2*p],   al[0][0], al[0][1], al[0][2], al[0][3], b0, b1);
                MMA_BF16(acc[1][2*p],   al[1][0], al[1][1], al[1][2], al[1][3], b0, b1);
                MMA_BF16(acc[0][2*p+1], ah[0][0], ah[0][1], ah[0][2], ah[0][3], b2, b3);
                MMA_BF16(acc[1][2*p+1], ah[1][0], ah[1][1], ah[1][2], ah[1][3], b2, b3);
                MMA_BF16(acc[0][2*p+1], al[0][0], al[0][1], al[0][2], al[0][3], b2, b3);
                MMA_BF16(acc[1][2*p+1], al[1][0], al[1][1], al[1][2], al[1][3], b2, b3);
            }
            // pass 3: Ahi x Blo
#pragma unroll
            for (int p = 0; p < 2; p++) {
                uint32_t b0, b1, b2, b3;
                LDSM_X4(b0, b1, b2, b3, aB + 8192 + p * 2048);
                MMA_BF16(acc[0][2*p],   ah[0][0], ah[0][1], ah[0][2], ah[0][3], b0, b1);
                MMA_BF16(acc[1][2*p],   ah[1][0], ah[1][1], ah[1][2], ah[1][3], b0, b1);
                MMA_BF16(acc[0][2*p+1], ah[0][0], ah[0][1], ah[0][2], ah[0][3], b2, b3);
                MMA_BF16(acc[1][2*p+1], ah[1][0], ah[1][1], ah[1][2], ah[1][3], b2, b3);
            }
        }
    }

    // ---- cross-K-split reduction: ks 1..3 -> smem(slot1), ks 0 sums ----
    const int sl = mg * 2 + js;                 // 0..3 (mg,js) slot
    if (ks != 0) {
        float4* dst = reinterpret_cast<float4*>(
            smem + SRED + (ks - 1) * REDLAYER + (sl * 32 + lane) * 128);
#pragma unroll
        for (int d = 0; d < 2; d++)
#pragma unroll
            for (int j = 0; j < 4; j++)
                dst[d * 4 + j] = make_float4(acc[d][j][0], acc[d][j][1],
                                             acc[d][j][2], acc[d][j][3]);
    }
    __syncthreads();
    float* trans = reinterpret_cast<float*>(smem);   // slot0: 64 x 64, stride 68
    if (ks == 0) {
#pragma unroll
        for (int d = 0; d < 2; d++)
#pragma unroll
            for (int j = 0; j < 4; j++) {
                float4 v = make_float4(acc[d][j][0], acc[d][j][1],
                                       acc[d][j][2], acc[d][j][3]);
#pragma unroll
                for (int l = 0; l < 3; l++) {
                    float4 u = reinterpret_cast<const float4*>(
                        smem + SRED + l * REDLAYER + (sl * 32 + lane) * 128)[d * 4 + j];
                    v.x += u.x; v.y += u.y; v.z += u.z; v.w += u.w;
                }
                int row0 = mg * 32 + d * 16 + r;
                int col  = (js * 4 + j) * 8 + 2 * cq;
                *reinterpret_cast<float2*>(&trans[row0 * 68 + col]) =
                    make_float2(v.x, v.y);
                *reinterpret_cast<float2*>(&trans[(row0 + 8) * 68 + col]) =
                    make_float2(v.z, v.w);
            }
    }
    __syncthreads();

    // ---- cell update: 1024 cells (16 hd x 64 b), 2 per thread ----
    {
        const int hd = tid >> 5, b0 = (tid & 31) * 2;          // hd 0..15
        const int hdim = mt * 16 + hd;
        const float* bp = g_biasp[ISL1 ? 1 : 0] + m * 128 + half * 64 + hd * 4;
        float2 gi = *reinterpret_cast<const float2*>(&trans[(hd * 4 + 0) * 68 + b0]);
        float2 gf = *reinterpret_cast<const float2*>(&trans[(hd * 4 + 1) * 68 + b0]);
        float2 gg = *reinterpret_cast<const float2*>(&trans[(hd * 4 + 2) * 68 + b0]);
        float2 go = *reinterpret_cast<const float2*>(&trans[(hd * 4 + 3) * 68 + b0]);
        float bi = bp[0], bf = bp[1], bg = bp[2], bo = bp[3];
        float iv[2] = {gi.x, gi.y};
        float fv[2] = {gf.x, gf.y};
        float gv[2] = {gg.x, gg.y};
        float ov[2] = {go.x, go.y};
        __nv_bfloat16* hout = ISL1 ? &g_h1t[tstep & 1][0][0] : &g_h0t[tstep & 1][0][0];
        const int kct = hdim >> 6, col = hdim & 63;
#pragma unroll
        for (int q = 0; q < 2; q++) {
            float is = 1.0f / (1.0f + expf(-(iv[q] + bi)));
            float fs = 1.0f / (1.0f + expf(-(fv[q] + bf)));
            float gt = tanhf(gv[q] + bg);
            float os = 1.0f / (1.0f + expf(-(ov[q] + bo)));
            float cn = fs * creg[q] + is * gt;
            creg[q] = cn;
            float h = os * tanhf(cn);
            int b = b0 + q;
            uint32_t off = sw128((uint32_t)(b * 128 + col * 2)) >> 1;
            __nv_bfloat16 hh = __float2bfloat16(h);
            hout[kct * 8192 + off] = hh;
            hout[kct * 8192 + 4096 + off] = __float2bfloat16(h - __bfloat162float(hh));
            if (ISL1 && tstep == TLEN - 1) g_h1final[b * HID + hdim] = h;
        }
    }
    __syncthreads();                 // trans reads done before slot0 reuse
    preissue_a0<ISL1>(sbase, m, half);  // overlap next step's A0 with barrier
}

__global__ void __launch_bounds__(NTHR, 1)
lstm_persistent_kernel()
{
    extern __shared__ __align__(1024) char smem[];
    uint32_t sbase = smem_u32(smem);
    const int tid = threadIdx.x;

    {   // zero h tile buffers (both parities)
        uint32_t* z0 = reinterpret_cast<uint32_t*>(&g_h0t[0][0][0]);
        uint32_t* z1 = reinterpret_cast<uint32_t*>(&g_h1t[0][0][0]);
        for (int i = blockIdx.x * NTHR + tid; i < 131072; i += NCTA * NTHR) {
            z0[i] = 0u; z1[i] = 0u;
        }
    }
    grid_barrier();

    const bool isl1 = blockIdx.x < 64;
    const int mt = isl1 ? blockIdx.x : blockIdx.x - 64;
    const int m = mt >> 1, half = mt & 1;
    float creg[2] = {0.f, 0.f};

    // initial A0 pre-issue for every CTA (consumed by its first run_step)
    if (isl1) preissue_a0<true>(sbase, m, half);
    else      preissue_a0<false>(sbase, m, half);

    if (!isl1)
        run_step<NCH0, false>(smem, sbase, mt, 0, creg);
    grid_barrier();

    for (int t = 0; t < TLEN; t++) {
        if (isl1)
            run_step<NCH1, true>(smem, sbase, mt, t, creg);
        else if (t + 1 < TLEN)
            run_step<NCH0, false>(smem, sbase, mt, t + 1, creg);
        grid_barrier();
    }
}

// ---------------- prep kernels (gate-permuted, swizzled, hi/lo split) -------
__device__ __forceinline__ void split_store(__nv_bfloat16* hp, __nv_bfloat16* lp, float w) {
    __nv_bfloat16 hi = __float2bfloat16(w);
    *hp = hi;
    *lp = __float2bfloat16(w - __bfloat162float(hi));
}

// combined W prep: blocks [0, 32768) -> W1, [32768, 51200) -> W0
__global__ void prep_w_kernel(const float* __restrict__ Wih1, const float* __restrict__ Whh1,
                              const float* __restrict__ Wih0, const float* __restrict__ Whh0) {
    if (blockIdx.x < 32768) {
        int idx = blockIdx.x * 256 + threadIdx.x;
        int c = idx & 63, r = (idx >> 6) & 127, kc = (idx >> 13) & 31, mm = idx >> 18;
        int orig = (r & 3) * 1024 + mm * 32 + (r >> 2);
        int kg = kc * 64 + c;
        float w = (kg < 1024) ? Wih1[orig * 1024 + kg] : Whh1[orig * 1024 + kg - 1024];
        int base = (mm * 32 + kc) * 16384;
        uint32_t off = sw128((uint32_t)(r * 128 + c * 2)) >> 1;
        split_store(&g_w1[base + off], &g_w1[base + 8192 + off], w);
    } else {
        int idx = (blockIdx.x - 32768) * 256 + threadIdx.x;
        int c = idx & 63, r = (idx >> 6) & 127;
        int rest = idx >> 13;
        int kc = rest % 18, mm = rest / 18;
        int orig = (r & 3) * 1024 + mm * 32 + (r >> 2);
        int kg = kc * 64 + c;
        float w = (kg < 128) ? Wih0[orig * 128 + kg] : Whh0[orig * 1024 + kg - 128];
        int base = (mm * 18 + kc) * 16384;
        uint32_t off = sw128((uint32_t)(r * 128 + c * 2)) >> 1;
        split_store(&g_w0[base + off], &g_w0[base + 8192 + off], w);
    }
}

__global__ void prep_x_kernel(const float* __restrict__ x) {
    int idx = blockIdx.x * 256 + threadIdx.x;            // 4194304
    int c = idx & 63, b = (idx >> 6) & 63, kc = (idx >> 12) & 1, t = idx >> 13;
    float v = x[b * (TLEN * 128) + t * 128 + kc * 64 + c];
    int base = (t * 2 + kc) * 8192;
    uint32_t off = sw128((uint32_t)(b * 128 + c * 2)) >> 1;
    split_store(&g_xt[base + off], &g_xt[base + 4096 + off], v);
}

__global__ void prep_bias_kernel(const float* __restrict__ bih0, const float* __restrict__ bhh0,
                                 const float* __restrict__ bih1, const float* __restrict__ bhh1) {
    int idx = blockIdx.x * 256 + threadIdx.x;            // 8192
    int l = idx >> 12, p = idx & 4095;
    int mm = p >> 7, r = p & 127;
    int orig = (r & 3) * 1024 + mm * 32 + (r >> 2);
    g_biasp[l][p] = l ? (bih1[orig] + bhh1[orig]) : (bih0[orig] + bhh0[orig]);
}

__global__ void lstm_fc_kernel(const float* __restrict__ h,
                               const float* __restrict__ w,
                               const float* __restrict__ bias,
                               float* __restrict__ out) {
    __shared__ float warpsum[8];
    int b = blockIdx.x, tid = threadIdx.x;
    float s = 0.0f;
    for (int mm = tid; mm < HID; mm += 256) s += h[b * HID + mm] * w[mm];
#pragma unroll
    for (int o = 16; o; o >>= 1) s += __shfl_down_sync(0xffffffffu, s, o);
    if ((tid & 31) == 0) warpsum[tid >> 5] = s;
    __syncthreads();
    if (tid == 0) {
        float t = 0.0f;
#pragma unroll
        for (int i = 0; i < 8; i++) t += warpsum[i];
        out[b] = t + bias[0];
    }
}

extern "C" void kernel_launch(void* const* d_in, const int* in_sizes, int n_in,
                              void* d_out, int out_size) {
    const float* x    = (const float*)d_in[0];
    const float* Wih0 = (const float*)d_in[1];
    const float* Whh0 = (const float*)d_in[2];
    const float* bih0 = (const float*)d_in[3];
    const float* bhh0 = (const float*)d_in[4];
    const float* Wih1 = (const float*)d_in[5];
    const float* Whh1 = (const float*)d_in[6];
    const float* bih1 = (const float*)d_in[7];
    const float* bhh1 = (const float*)d_in[8];
    const float* fcw  = (const float*)d_in[9];
    const float* fcb  = (const float*)d_in[10];
    float* out = (float*)d_out;

    cudaFuncSetAttribute(lstm_persistent_kernel,
                         cudaFuncAttributeMaxDynamicSharedMemorySize, SMEM_TOTAL);
    float* h1f;
    cudaGetSymbolAddress((void**)&h1f, g_h1final);

    // persistent kernel deliberately the 4th launch (ncu capture slot)
    prep_bias_kernel<<<32, 256>>>(bih0, bhh0, bih1, bhh1);
    prep_w_kernel<<<51200, 256>>>(Wih1, Whh1, Wih0, Whh0);
    prep_x_kernel<<<16384, 256>>>(x);
    lstm_persistent_kernel<<<NCTA, NTHR, SMEM_TOTAL>>>();
    lstm_fc_kernel<<<64, 256>>>(h1f, fcw, fcb, out);
}

// round 17
// speedup vs baseline: 1.3509x; 1.3509x over previous
#include <cuda_runtime.h>
#include <cuda_bf16.h>
#include <cstdint>

#define BATCH 64
#define HID   1024
#define TLEN  512
#define NCTA  128
#define NTHR  512
#define NCH1  32   // layer1 K chunks of 64 (K = 1024 h0 + 1024 h1)
#define NCH0  18   // layer0 K chunks of 64 (K = 128 x + 1024 h0)

// Pre-tiled, pre-swizzled operands (gate-permuted rows, SW128, hi/lo split).
__device__ __align__(16) __nv_bfloat16 g_w1[32 * NCH1 * 16384];
__device__ __align__(16) __nv_bfloat16 g_w0[32 * NCH0 * 16384];
__device__ __align__(16) __nv_bfloat16 g_xt[TLEN * 2 * 8192];
__device__ __align__(16) __nv_bfloat16 g_h0t[2][16][8192];
__device__ __align__(16) __nv_bfloat16 g_h1t[2][16][8192];
__device__ float g_biasp[2][4096];
__device__ float g_h1final[BATCH * HID];
__device__ unsigned g_bar_count, g_bar_gen;

__host__ __device__ __forceinline__ uint32_t sw128(uint32_t o) {
    return o ^ ((o >> 3) & 0x70);
}

// smem: 3 staging slots (A 16KB + B 16KB each) | 4 reduction layers
// (conflict-free [idx][sl][lane] float4) | dedicated trans buffer.
#define SLOT(s)   ((s) * 32768)
#define SRED      98304
#define REDLAYER  16384
#define STRANS    163840                        // 64 x 68 floats = 17408 B
#define SMEM_TOTAL 181248

__device__ __forceinline__ uint32_t smem_u32(const void* p) {
    uint32_t a;
    asm("{ .reg .u64 t; cvta.to.shared.u64 t, %1; cvt.u32.u64 %0, t; }" : "=r"(a) : "l"(p));
    return a;
}
#define CP_ASYNC16(dst_u32, src_ptr) \
    asm volatile("cp.async.cg.shared.global [%0], [%1], 16;" \
                 :: "r"(dst_u32), "l"(src_ptr) : "memory")
#define CP_COMMIT() asm volatile("cp.async.commit_group;" ::: "memory")
#define CP_WAIT1()  asm volatile("cp.async.wait_group 1;" ::: "memory")
#define CP_WAIT0()  asm volatile("cp.async.wait_group 0;" ::: "memory")

#define LDSM_X4(r0, r1, r2, r3, addr) \
    asm volatile("ldmatrix.sync.aligned.m8n8.x4.shared.b16 {%0,%1,%2,%3}, [%4];" \
                 : "=r"(r0), "=r"(r1), "=r"(r2), "=r"(r3) : "r"(addr))

__device__ __forceinline__ void grid_barrier() {
    __syncthreads();
    if (threadIdx.x == 0) {
        __threadfence();
        unsigned gen = *(volatile unsigned*)&g_bar_gen;
        if (atomicAdd(&g_bar_count, 1u) == NCTA - 1) {
            g_bar_count = 0;
            __threadfence();
            *(volatile unsigned*)&g_bar_gen = gen + 1;
        } else {
            while (*(volatile unsigned*)&g_bar_gen == gen) {}
            __threadfence();
        }
    }
    __syncthreads();
}

#define MMA_BF16(d, a0, a1, a2, a3, b0, b1)                                 \
    asm volatile("mma.sync.aligned.m16n8k16.row.col.f32.bf16.bf16.f32 "     \
                 "{%0,%1,%2,%3}, {%4,%5,%6,%7}, {%8,%9}, {%0,%1,%2,%3};"    \
                 : "+f"((d)[0]), "+f"((d)[1]), "+f"((d)[2]), "+f"((d)[3])   \
                 : "r"(a0), "r"(a1), "r"(a2), "r"(a3), "r"(b0), "r"(b1))

// Pre-issue chunk-0's A planes into slot 0 (step-invariant addresses).
template <bool ISL1>
__device__ __forceinline__ void preissue_a0(uint32_t sbase, int m, int half) {
    const __nv_bfloat16* wtile = ISL1 ? (g_w1 + m * NCH1 * 16384)
                                      : (g_w0 + m * NCH0 * 16384);
    const int tid = threadIdx.x;
    const char* ga_hi = reinterpret_cast<const char*>(wtile + half * 4096);
    const char* ga_lo = ga_hi + 16384;           // +8192 elements (lo plane)
    uint32_t da = sbase + SLOT(0);
    CP_ASYNC16(da + tid * 16, ga_hi + tid * 16);
    CP_ASYNC16(da + 8192 + tid * 16, ga_lo + tid * 16);
    CP_COMMIT();
}

// One step, one CTA: 64 gate rows (= 16 hidden dims) x 64 batches, full K.
// 16 warps = 2 m-groups x 4 K-splits x 2 j-splits (32 batches each).
// mt = tile index 0..63: m = mt>>1 (128-row weight tile), half = mt&1.
template <int NCH, bool ISL1>
__device__ __forceinline__ void
run_step(char* smem, uint32_t sbase, int mt, int tstep, float* creg)
{
    const int tid  = threadIdx.x;
    const int wid  = tid >> 5, lane = tid & 31;
    const int mg   = wid & 1,  ks   = (wid >> 1) & 3, js = wid >> 3;
    const int m    = mt >> 1,  half = mt & 1;

    const __nv_bfloat16* wtile = ISL1 ? (g_w1 + m * NCH1 * 16384)
                                      : (g_w0 + m * NCH0 * 16384);
    auto bsrc_of = [&](int kc) -> const __nv_bfloat16* {
        if (ISL1) return (kc < 16) ? &g_h0t[tstep & 1][kc][0]
                                   : &g_h1t[(tstep + 1) & 1][kc - 16][0];
        else      return (kc < 2)  ? &g_xt[(tstep * 2 + kc) * 8192]
                                   : &g_h0t[(tstep + 1) & 1][kc - 2][0];
    };

    // async staging: A hi 8KB + A lo 8KB + B hi 8KB + B lo 8KB; 4 x 16B/thread
    auto issue = [&](int kc) {
        const int s = kc % 3;
        const char* ga_hi = reinterpret_cast<const char*>(
            wtile + kc * 16384 + half * 4096);
        const char* ga_lo = ga_hi + 16384;       // +8192 elements
        const char* gb = reinterpret_cast<const char*>(bsrc_of(kc));
        uint32_t da = sbase + SLOT(s);
        uint32_t db = da + 16384;
        CP_ASYNC16(da + tid * 16, ga_hi + tid * 16);
        CP_ASYNC16(da + 8192 + tid * 16, ga_lo + tid * 16);
        CP_ASYNC16(db + tid * 16, gb + tid * 16);
        CP_ASYNC16(db + 8192 + tid * 16, gb + 8192 + tid * 16);
        CP_COMMIT();
    };

    float acc[2][4][4];
#pragma unroll
    for (int d = 0; d < 2; d++)
#pragma unroll
        for (int j = 0; j < 4; j++)
#pragma unroll
            for (int q = 0; q < 4; q++) acc[d][j][q] = 0.0f;

    // Chunk-invariant per-lane ldmatrix addresses (validated R14/R15).
    const int grp = lane >> 3, rowin = lane & 7;
    const uint32_t aoff =
        (uint32_t)((mg * 32 + ((grp & 1) << 3) + rowin) * 128) +
        ((uint32_t)(ks * 32 + ((grp >> 1) << 4)) ^ (uint32_t)(rowin << 4));
    const uint32_t boff =
        (uint32_t)((((grp >> 1) << 3) + rowin) * 128) +
        ((uint32_t)(ks * 32 + ((grp & 1) << 4)) ^ (uint32_t)(rowin << 4)) +
        (uint32_t)(js * 4096);

    // A0 already pre-issued (tail of previous step / prologue). Fetch B0 only.
    {
        const char* gb = reinterpret_cast<const char*>(bsrc_of(0));
        uint32_t db = sbase + SLOT(0) + 16384;
        CP_ASYNC16(db + tid * 16, gb + tid * 16);
        CP_ASYNC16(db + 8192 + tid * 16, gb + 8192 + tid * 16);
        CP_COMMIT();
    }
    issue(1);

    for (int kc = 0; kc < NCH; kc++) {
        if (kc + 1 < NCH) CP_WAIT1(); else CP_WAIT0();
        __syncthreads();                       // slot kc%3 full; kc-1 reads done
        if (kc + 2 < NCH) issue(kc + 2);       // overwrites slot (kc-1)%3: safe

        const uint32_t sb = sbase + SLOT(kc % 3);
        const uint32_t aA = sb + aoff;         // A hi; lo at +8192
        const uint32_t aB = sb + 16384 + boff; // B hi; lo at +8192

        uint32_t ah[2][4], al[2][4];
        LDSM_X4(ah[0][0], ah[0][1], ah[0][2], ah[0][3], aA);
        LDSM_X4(ah[1][0], ah[1][1], ah[1][2], ah[1][3], aA + 2048);
        LDSM_X4(al[0][0], al[0][1], al[0][2], al[0][3], aA + 8192);
        LDSM_X4(al[1][0], al[1][1], al[1][2], al[1][3], aA + 8192 + 2048);

        // passes 1+2: (Ahi + Alo) x Bhi — this warp's 2 n16 pairs
#pragma unroll
        for (int p = 0; p < 2; p++) {
            uint32_t b0, b1, b2, b3;
            LDSM_X4(b0, b1, b2, b3, aB + p * 2048);
            MMA_BF16(acc[0][2*p],   ah[0][0], ah[0][1], ah[0][2], ah[0][3], b0, b1);
            MMA_BF16(acc[1][2*p],   ah[1][0], ah[1][1], ah[1][2], ah[1][3], b0, b1);
            MMA_BF16(acc[0][2*p],   al[0][0], al[0][1], al[0][2], al[0][3], b0, b1);
            MMA_BF16(acc[1][2*p],   al[1][0], al[1][1], al[1][2], al[1][3], b0, b1);
            MMA_BF16(acc[0][2*p+1], ah[0][0], ah[0][1], ah[0][2], ah[0][3], b2, b3);
            MMA_BF16(acc[1][2*p+1], ah[1][0], ah[1][1], ah[1][2], ah[1][3], b2, b3);
            MMA_BF16(acc[0][2*p+1], al[0][0], al[0][1], al[0][2], al[0][3], b2, b3);
            MMA_BF16(acc[1][2*p+1], al[1][0], al[1][1], al[1][2], al[1][3], b2, b3);
        }
        // pass 3: Ahi x Blo
#pragma unroll
        for (int p = 0; p < 2; p++) {
            uint32_t b0, b1, b2, b3;
            LDSM_X4(b0, b1, b2, b3, aB + 8192 + p * 2048);
            MMA_BF16(acc[0][2*p],   ah[0][0], ah[0][1], ah[0][2], ah[0][3], b0, b1);
            MMA_BF16(acc[1][2*p],   ah[1][0], ah[1][1], ah[1][2], ah[1][3], b0, b1);
            MMA_BF16(acc[0][2*p+1], ah[0][0], ah[0][1], ah[0][2], ah[0][3], b2, b3);
            MMA_BF16(acc[1][2*p+1], ah[1][0], ah[1][1], ah[1][2], ah[1][3], b2, b3);
        }
    }

    // Overlap next step's A0 fetch with the epilogue + grid barrier.
    // slot0's last reader was chunk NCH-3; the kc=NCH-1 sync covered it.
    preissue_a0<ISL1>(sbase, m, half);

    // ---- cross-K-split reduction (conflict-free, all 16 warps) ----
    // Layer ks layout: [idx(d*4+j)][sl][lane] float4, lane-contiguous.
    const int sl = mg * 2 + js;                 // 0..3 (mg,js) slot
    {
        float4* dst = reinterpret_cast<float4*>(smem + SRED + ks * REDLAYER);
        const int base = sl * 32 + lane;
#pragma unroll
        for (int d = 0; d < 2; d++)
#pragma unroll
            for (int j = 0; j < 4; j++)
                dst[(d * 4 + j) * 128 + base] =
                    make_float4(acc[d][j][0], acc[d][j][1],
                                acc[d][j][2], acc[d][j][3]);
    }
    __syncthreads();
    float* trans = reinterpret_cast<float*>(smem + STRANS);  // 64 x 64, stride 68
    {
        // each thread sums 2 outputs across the 4 layers
        const int sl2 = wid & 3, i0 = (wid >> 2) * 2;
        const int mg2 = sl2 >> 1, js2 = sl2 & 1;
        const int r2 = lane >> 2, cq2 = lane & 3;
#pragma unroll
        for (int ii = 0; ii < 2; ii++) {
            const int idx = i0 + ii;
            const int pos = idx * 128 + sl2 * 32 + lane;
            float4 v = reinterpret_cast<const float4*>(smem + SRED)[pos];
#pragma unroll
            for (int l = 1; l < 4; l++) {
                float4 u = reinterpret_cast<const float4*>(
                    smem + SRED + l * REDLAYER)[pos];
                v.x += u.x; v.y += u.y; v.z += u.z; v.w += u.w;
            }
            const int d = idx >> 2, j = idx & 3;
            const int row0 = mg2 * 32 + d * 16 + r2;
            const int col  = (js2 * 4 + j) * 8 + 2 * cq2;
            *reinterpret_cast<float2*>(&trans[row0 * 68 + col]) =
                make_float2(v.x, v.y);
            *reinterpret_cast<float2*>(&trans[(row0 + 8) * 68 + col]) =
                make_float2(v.z, v.w);
        }
    }
    __syncthreads();

    // ---- cell update: 1024 cells (16 hd x 64 b), 2 per thread ----
    {
        const int hd = tid >> 5, b0 = (tid & 31) * 2;          // hd 0..15
        const int hdim = mt * 16 + hd;
        const float* bp = g_biasp[ISL1 ? 1 : 0] + m * 128 + half * 64 + hd * 4;
        float2 gi = *reinterpret_cast<const float2*>(&trans[(hd * 4 + 0) * 68 + b0]);
        float2 gf = *reinterpret_cast<const float2*>(&trans[(hd * 4 + 1) * 68 + b0]);
        float2 gg = *reinterpret_cast<const float2*>(&trans[(hd * 4 + 2) * 68 + b0]);
        float2 go = *reinterpret_cast<const float2*>(&trans[(hd * 4 + 3) * 68 + b0]);
        float bi = bp[0], bf = bp[1], bg = bp[2], bo = bp[3];
        float iv[2] = {gi.x, gi.y};
        float fv[2] = {gf.x, gf.y};
        float gv[2] = {gg.x, gg.y};
        float ov[2] = {go.x, go.y};
        __nv_bfloat16* hout = ISL1 ? &g_h1t[tstep & 1][0][0] : &g_h0t[tstep & 1][0][0];
        const int kct = hdim >> 6, col = hdim & 63;
#pragma unroll
        for (int q = 0; q < 2; q++) {
            float is = 1.0f / (1.0f + expf(-(iv[q] + bi)));
            float fs = 1.0f / (1.0f + expf(-(fv[q] + bf)));
            float gt = tanhf(gv[q] + bg);
            float os = 1.0f / (1.0f + expf(-(ov[q] + bo)));
            float cn = fs * creg[q] + is * gt;
            creg[q] = cn;
            float h = os * tanhf(cn);
            int b = b0 + q;
            uint32_t off = sw128((uint32_t)(b * 128 + col * 2)) >> 1;
            __nv_bfloat16 hh = __float2bfloat16(h);
            hout[kct * 8192 + off] = hh;
            hout[kct * 8192 + 4096 + off] = __float2bfloat16(h - __bfloat162float(hh));
            if (ISL1 && tstep == TLEN - 1) g_h1final[b * HID + hdim] = h;
        }
    }
}

__global__ void __launch_bounds__(NTHR, 1)
lstm_persistent_kernel()
{
    extern __shared__ __align__(1024) char smem[];
    uint32_t sbase = smem_u32(smem);
    const int tid = threadIdx.x;

    {   // zero h tile buffers (both parities)
        uint32_t* z0 = reinterpret_cast<uint32_t*>(&g_h0t[0][0][0]);
        uint32_t* z1 = reinterpret_cast<uint32_t*>(&g_h1t[0][0][0]);
        for (int i = blockIdx.x * NTHR + tid; i < 131072; i += NCTA * NTHR) {
            z0[i] = 0u; z1[i] = 0u;
        }
    }
    grid_barrier();

    const bool isl1 = blockIdx.x < 64;
    const int mt = isl1 ? blockIdx.x : blockIdx.x - 64;
    const int m = mt >> 1, half = mt & 1;
    float creg[2] = {0.f, 0.f};

    // prologue A0 pre-issue (consumed by this CTA's first run_step)
    if (isl1) preissue_a0<true>(sbase, m, half);
    else      preissue_a0<false>(sbase, m, half);

    if (!isl1)
        run_step<NCH0, false>(smem, sbase, mt, 0, creg);
    grid_barrier();

    for (int t = 0; t < TLEN; t++) {
        if (isl1)
            run_step<NCH1, true>(smem, sbase, mt, t, creg);
        else if (t + 1 < TLEN)
            run_step<NCH0, false>(smem, sbase, mt, t + 1, creg);
        grid_barrier();
    }
    CP_WAIT0();        // drain the final (unconsumed) pre-issued A0 group
}

// ---------------- prep kernels (gate-permuted, swizzled, hi/lo split) -------
__device__ __forceinline__ void split_store(__nv_bfloat16* hp, __nv_bfloat16* lp, float w) {
    __nv_bfloat16 hi = __float2bfloat16(w);
    *hp = hi;
    *lp = __float2bfloat16(w - __bfloat162float(hi));
}

// combined W prep: blocks [0, 32768) -> W1, [32768, 51200) -> W0
__global__ void prep_w_kernel(const float* __restrict__ Wih1, const float* __restrict__ Whh1,
                              const float* __restrict__ Wih0, const float* __restrict__ Whh0) {
    if (blockIdx.x < 32768) {
        int idx = blockIdx.x * 256 + threadIdx.x;
        int c = idx & 63, r = (idx >> 6) & 127, kc = (idx >> 13) & 31, mm = idx >> 18;
        int orig = (r & 3) * 1024 + mm * 32 + (r >> 2);
        int kg = kc * 64 + c;
        float w = (kg < 1024) ? Wih1[orig * 1024 + kg] : Whh1[orig * 1024 + kg - 1024];
        int base = (mm * NCH1 + kc) * 16384;
        uint32_t off = sw128((uint32_t)(r * 128 + c * 2)) >> 1;
        split_store(&g_w1[base + off], &g_w1[base + 8192 + off], w);
    } else {
        int idx = (blockIdx.x - 32768) * 256 + threadIdx.x;
        int c = idx & 63, r = (idx >> 6) & 127;
        int rest = idx >> 13;
        int kc = rest % NCH0, mm = rest / NCH0;
        int orig = (r & 3) * 1024 + mm * 32 + (r >> 2);
        int kg = kc * 64 + c;
        float w = (kg < 128) ? Wih0[orig * 128 + kg] : Whh0[orig * 1024 + kg - 128];
        int base = (mm * NCH0 + kc) * 16384;
        uint32_t off = sw128((uint32_t)(r * 128 + c * 2)) >> 1;
        split_store(&g_w0[base + off], &g_w0[base + 8192 + off], w);
    }
}

__global__ void prep_x_kernel(const float* __restrict__ x) {
    int idx = blockIdx.x * 256 + threadIdx.x;            // 4194304
    int c = idx & 63, b = (idx >> 6) & 63, kc = (idx >> 12) & 1, t = idx >> 13;
    float v = x[b * (TLEN * 128) + t * 128 + kc * 64 + c];
    int base = (t * 2 + kc) * 8192;
    uint32_t off = sw128((uint32_t)(b * 128 + c * 2)) >> 1;
    split_store(&g_xt[base + off], &g_xt[base + 4096 + off], v);
}

__global__ void prep_bias_kernel(const float* __restrict__ bih0, const float* __restrict__ bhh0,
                                 const float* __restrict__ bih1, const float* __restrict__ bhh1) {
    int idx = blockIdx.x * 256 + threadIdx.x;            // 8192
    int l = idx >> 12, p = idx & 4095;
    int mm = p >> 7, r = p & 127;
    int orig = (r & 3) * 1024 + mm * 32 + (r >> 2);
    g_biasp[l][p] = l ? (bih1[orig] + bhh1[orig]) : (bih0[orig] + bhh0[orig]);
}

__global__ void lstm_fc_kernel(const float* __restrict__ h,
                               const float* __restrict__ w,
                               const float* __restrict__ bias,
                               float* __restrict__ out) {
    __shared__ float warpsum[8];
    int b = blockIdx.x, tid = threadIdx.x;
    float s = 0.0f;
    for (int mm = tid; mm < HID; mm += 256) s += h[b * HID + mm] * w[mm];
#pragma unroll
    for (int o = 16; o; o >>= 1) s += __shfl_down_sync(0xffffffffu, s, o);
    if ((tid & 31) == 0) warpsum[tid >> 5] = s;
    __syncthreads();
    if (tid == 0) {
        float t = 0.0f;
#pragma unroll
        for (int i = 0; i < 8; i++) t += warpsum[i];
        out[b] = t + bias[0];
    }
}

extern "C" void kernel_launch(void* const* d_in, const int* in_sizes, int n_in,
                              void* d_out, int out_size) {
    const float* x    = (const float*)d_in[0];
    const float* Wih0 = (const float*)d_in[1];
    const float* Whh0 = (const float*)d_in[2];
    const float* bih0 = (const float*)d_in[3];
    const float* bhh0 = (const float*)d_in[4];
    const float* Wih1 = (const float*)d_in[5];
    const float* Whh1 = (const float*)d_in[6];
    const float* bih1 = (const float*)d_in[7];
    const float* bhh1 = (const float*)d_in[8];
    const float* fcw  = (const float*)d_in[9];
    const float* fcb  = (const float*)d_in[10];
    float* out = (float*)d_out;

    cudaFuncSetAttribute(lstm_persistent_kernel,
                         cudaFuncAttributeMaxDynamicSharedMemorySize, SMEM_TOTAL);
    float* h1f;
    cudaGetSymbolAddress((void**)&h1f, g_h1final);

    // persistent kernel deliberately the 4th launch (ncu capture slot)
    prep_bias_kernel<<<32, 256>>>(bih0, bhh0, bih1, bhh1);
    prep_w_kernel<<<51200, 256>>>(Wih1, Whh1, Wih0, Whh0);
    prep_x_kernel<<<16384, 256>>>(x);
    lstm_persistent_kernel<<<NCTA, NTHR, SMEM_TOTAL>>>();
    lstm_fc_kernel<<<64, 256>>>(h1f, fcw, fcb, out);
}